// round 12
// baseline (speedup 1.0000x reference)
#include <cuda_runtime.h>
#include <math.h>

#define NB 32
#define NC 256
#define NH 56
#define NW 56
#define NP 49
#define CMID 64
#define NSL 8            // conv1 split-K slices (32 channels each)

// ---------------- scratch ----------------
__device__ float g_pooled[NB * NC * NP];
__device__ float g_w1t[2304 * CMID];            // [k=c*9+t][oc]
__device__ float g_w2d[576 * NC];               // [k=c*9+t][oc] (diff oc - (oc+256))
__device__ float g_b2d[NC];
__device__ float g_c1part[NB * CMID * NP * NSL];
__device__ float g_l2part[NB * NC * NP * 2];    // conv2-diff partials (2 ic-slices)

#define W1N (CMID * 2304)
#define W2DN (NC * 576)
#define WTN (W1N + W2DN + NC)
#define POOLBLKS (NB * NC)
#define WTBLKS ((WTN + 415) / 416)

// ---------------- kernel 0: pool (56x56 -> 7x7)  ||  weight prep ----------------
__global__ void prep_kernel(const float* __restrict__ x, const float* __restrict__ w1,
                            const float* __restrict__ w2, const float* __restrict__ b2) {
    const int tid = threadIdx.x;
    if (blockIdx.x < POOLBLKS) {
        __shared__ float srow[392];
        const int bc = blockIdx.x;
        if (tid < 392) {
            const int r = tid / 7, s = tid % 7;
            const float4* p = reinterpret_cast<const float4*>(
                x + (size_t)bc * (NH * NW) + r * NW + s * 8);
            float4 v0 = p[0], v1 = p[1];
            srow[tid] = (v0.x + v0.y + v0.z + v0.w) + (v1.x + v1.y + v1.z + v1.w);
        }
        __syncthreads();
        if (tid < NP) {
            const int wi = tid / 7, wj = tid % 7;
            float s = 0.f;
#pragma unroll
            for (int k = 0; k < 8; k++) s += srow[(wi * 8 + k) * 7 + wj];
            g_pooled[bc * NP + tid] = s * (1.0f / 64.0f);
        }
    } else {
        const int i = (blockIdx.x - POOLBLKS) * 416 + tid;
        if (i < W1N) {
            int oc = i / 2304, k = i % 2304;
            g_w1t[k * CMID + oc] = w1[i];
        } else if (i < W1N + W2DN) {
            int j = i - W1N;
            int oc = j / 576, k = j % 576;
            g_w2d[k * NC + oc] = w2[oc * 576 + k] - w2[(oc + 256) * 576 + k];
        } else if (i < WTN) {
            int oc = i - W1N - W2DN;
            g_b2d[oc] = b2[oc] - b2[oc + 256];
        }
    }
}

// ---------------- kernel 1: conv1 3x3 (256->64), split-K=8 ----------------
__global__ void __launch_bounds__(224, 2) conv1_kernel() {
    __shared__ float s_act[8 * 108];
    __shared__ float s_w[4608];
    const int sl = blockIdx.x, b = blockIdx.y;
    const int tid = threadIdx.x;
    const int r = tid >> 5, lane = tid & 31;

    float acc0[7], acc1[7];
#pragma unroll
    for (int i = 0; i < 7; i++) { acc0[i] = 0.f; acc1[i] = 0.f; }

    for (int chunk = 0; chunk < 4; chunk++) {
        __syncthreads();
        const int c0 = sl * 32 + chunk * 8;
        for (int idx = tid; idx < 8 * 81; idx += 224) {
            const int c = idx / 81, pp = idx % 81;
            const int pr = pp / 9, pc = pp % 9;
            float v = 0.f;
            if (pr >= 1 && pr <= 7 && pc >= 1 && pc <= 7)
                v = g_pooled[(b * NC + c0 + c) * NP + (pr - 1) * 7 + (pc - 1)];
            s_act[c * 108 + pr * 12 + pc] = v;
        }
        {
            const float4* src = reinterpret_cast<const float4*>(g_w1t + c0 * 9 * CMID);
            float4* dst = reinterpret_cast<float4*>(s_w);
            for (int idx = tid; idx < 1152; idx += 224) dst[idx] = src[idx];
        }
        __syncthreads();

#pragma unroll
        for (int cl = 0; cl < 8; cl++) {
            float aa[3][9];
#pragma unroll
            for (int ti = 0; ti < 3; ti++) {
                const float* rp = s_act + cl * 108 + (r + ti) * 12;
                float4 v0 = *reinterpret_cast<const float4*>(rp);
                float4 v1 = *reinterpret_cast<const float4*>(rp + 4);
                aa[ti][0] = v0.x; aa[ti][1] = v0.y; aa[ti][2] = v0.z; aa[ti][3] = v0.w;
                aa[ti][4] = v1.x; aa[ti][5] = v1.y; aa[ti][6] = v1.z; aa[ti][7] = v1.w;
                aa[ti][8] = rp[8];
            }
#pragma unroll
            for (int ti = 0; ti < 3; ti++) {
#pragma unroll
                for (int tj = 0; tj < 3; tj++) {
                    const float2 w = *reinterpret_cast<const float2*>(
                        s_w + (cl * 9 + ti * 3 + tj) * 64 + lane * 2);
#pragma unroll
                    for (int pj = 0; pj < 7; pj++) {
                        acc0[pj] = fmaf(aa[ti][pj + tj], w.x, acc0[pj]);
                        acc1[pj] = fmaf(aa[ti][pj + tj], w.y, acc1[pj]);
                    }
                }
            }
        }
    }
#pragma unroll
    for (int pj = 0; pj < 7; pj++) {
        const int p = r * 7 + pj;
        g_c1part[((size_t)(b * CMID + lane * 2) * NP + p) * NSL + sl] = acc0[pj];
        g_c1part[((size_t)(b * CMID + lane * 2 + 1) * NP + p) * NSL + sl] = acc1[pj];
    }
}

// ---------------- kernel 2: conv2-diff 3x3 (64->256), fused reduce+BN+GELU ----------------
__global__ void __launch_bounds__(224, 2) conv2_kernel(const float* __restrict__ gamma,
                                                       const float* __restrict__ beta) {
    __shared__ float s_act[8 * 108];
    __shared__ float s_w[4608];
    const int ot = blockIdx.x, ks = blockIdx.y, b = blockIdx.z;
    const int tid = threadIdx.x;
    const int r = tid >> 5, lane = tid & 31;

    float acc0[7], acc1[7];
#pragma unroll
    for (int i = 0; i < 7; i++) { acc0[i] = 0.f; acc1[i] = 0.f; }

    for (int chunk = 0; chunk < 4; chunk++) {
        __syncthreads();
        const int ic0 = ks * 32 + chunk * 8;
        for (int idx = tid; idx < 8 * 81; idx += 224) {
            const int c = idx / 81, pp = idx % 81;
            const int pr = pp / 9, pc = pp % 9;
            float v = 0.f;
            if (pr >= 1 && pr <= 7 && pc >= 1 && pc <= 7) {
                const int mid = ic0 + c;
                const float4* p8 = reinterpret_cast<const float4*>(
                    g_c1part + ((size_t)(b * CMID + mid) * NP + (pr - 1) * 7 + (pc - 1)) * NSL);
                float4 u = p8[0], w4 = p8[1];
                float s = ((u.x + u.y) + (u.z + u.w)) + ((w4.x + w4.y) + (w4.z + w4.w));
                float h = s * (gamma[mid] * rsqrtf(1.0f + 1e-5f)) + beta[mid];
                v = 0.5f * h * (1.0f + erff(h * 0.70710678118654752f));
            }
            s_act[c * 108 + pr * 12 + pc] = v;
        }
        for (int idx = tid; idx < 1152; idx += 224) {
            const int kk = idx >> 4, c4 = idx & 15;
            reinterpret_cast<float4*>(s_w)[idx] = *reinterpret_cast<const float4*>(
                g_w2d + (ic0 * 9 + kk) * NC + ot * 64 + c4 * 4);
        }
        __syncthreads();

#pragma unroll
        for (int cl = 0; cl < 8; cl++) {
            float aa[3][9];
#pragma unroll
            for (int ti = 0; ti < 3; ti++) {
                const float* rp = s_act + cl * 108 + (r + ti) * 12;
                float4 v0 = *reinterpret_cast<const float4*>(rp);
                float4 v1 = *reinterpret_cast<const float4*>(rp + 4);
                aa[ti][0] = v0.x; aa[ti][1] = v0.y; aa[ti][2] = v0.z; aa[ti][3] = v0.w;
                aa[ti][4] = v1.x; aa[ti][5] = v1.y; aa[ti][6] = v1.z; aa[ti][7] = v1.w;
                aa[ti][8] = rp[8];
            }
#pragma unroll
            for (int ti = 0; ti < 3; ti++) {
#pragma unroll
                for (int tj = 0; tj < 3; tj++) {
                    const float2 w = *reinterpret_cast<const float2*>(
                        s_w + (cl * 9 + ti * 3 + tj) * 64 + lane * 2);
#pragma unroll
                    for (int pj = 0; pj < 7; pj++) {
                        acc0[pj] = fmaf(aa[ti][pj + tj], w.x, acc0[pj]);
                        acc1[pj] = fmaf(aa[ti][pj + tj], w.y, acc1[pj]);
                    }
                }
            }
        }
    }

    const int oc0 = ot * 64 + lane * 2;
#pragma unroll
    for (int pj = 0; pj < 7; pj++) {
        const int p = r * 7 + pj;
        g_l2part[((size_t)(b * NC + oc0) * NP + p) * 2 + ks] = acc0[pj];
        g_l2part[((size_t)(b * NC + oc0 + 1) * NP + p) * 2 + ks] = acc1[pj];
    }
}

// ---------------- kernel 3: dw 7x7 depthwise, transposed tile + LDS.64 ----------------
// block 224 = 4 row-groups x 56 cols; thread = 14 rows x 1 col.
// xt[col][row], stride 66 (even -> float2-aligned; 66%32=2 -> conflict-free LDS.64
// under half-warp phasing). Fill loop uses incremental rr/cc (no div/mod).
#define TSTR 66
__global__ void __launch_bounds__(224, 8) dw_kernel(const float* __restrict__ x,
                                                    const float* __restrict__ wdyn,
                                                    float* __restrict__ y) {
    __shared__ float xt[62 * TSTR];
    __shared__ float ws[49];
    const int bc = blockIdx.x;
    const int tid = threadIdx.x;

    const float* xp = x + (size_t)bc * (NH * NW);
    {
        int rr = tid / 62, cc = tid - rr * 62;
#pragma unroll
        for (int it = 0; it < 18; it++) {
            const int idx = it * 224 + tid;
            if (idx < 62 * 62) {
                const int gr = rr - 3, gc = cc - 3;
                float v = 0.f;
                if ((unsigned)gr < 56u && (unsigned)gc < 56u) v = xp[gr * 56 + gc];
                xt[cc * TSTR + rr] = v;
            }
            rr += 3; cc += 38;
            if (cc >= 62) { cc -= 62; rr += 1; }
        }
    }
    if (tid < 49) {
        const int c = bc & (NC - 1);
        const float2 lp = *reinterpret_cast<const float2*>(g_l2part + ((size_t)bc * NP + tid) * 2);
        const float ld = lp.x + lp.y + g_b2d[c];
        const float s = 1.0f / (1.0f + expf(-ld));
        const float w0 = wdyn[c * NP + tid];
        const float w1 = wdyn[NC * NP + c * NP + tid];
        ws[tid] = s * w0 + (1.0f - s) * w1;
    }
    __syncthreads();

    const int cg = tid / 56;       // 0..3 -> rows cg*14 .. cg*14+13
    const int col = tid % 56;
    const int rbase = cg * 14;     // even -> aligned float2 reads

    float acc[14];
#pragma unroll
    for (int k = 0; k < 14; k++) acc[k] = 0.f;

#pragma unroll
    for (int dj = 0; dj < 7; dj++) {
        float ww[7];
#pragma unroll
        for (int di = 0; di < 7; di++) ww[di] = ws[di * 7 + dj];
        const float2* bp = reinterpret_cast<const float2*>(xt + (col + dj) * TSTR + rbase);
#pragma unroll
        for (int m2 = 0; m2 < 10; m2++) {
            const float2 v = bp[m2];
            const int m0 = 2 * m2, m1 = 2 * m2 + 1;
#pragma unroll
            for (int di = 0; di < 7; di++) {
                const int k0 = m0 - di;
                if (k0 >= 0 && k0 < 14) acc[k0] = fmaf(v.x, ww[di], acc[k0]);
                const int k1 = m1 - di;
                if (k1 >= 0 && k1 < 14) acc[k1] = fmaf(v.y, ww[di], acc[k1]);
            }
        }
    }
    float* yp = y + (size_t)bc * (NH * NW);
#pragma unroll
    for (int k = 0; k < 14; k++)
        yp[(cg * 14 + k) * 56 + col] = acc[k];
}

// ---------------- launch ----------------
extern "C" void kernel_launch(void* const* d_in, const int* in_sizes, int n_in,
                              void* d_out, int out_size) {
    const float* x     = (const float*)d_in[0];
    const float* wdyn  = (const float*)d_in[1];
    const float* w1    = (const float*)d_in[2];
    const float* gamma = (const float*)d_in[3];
    const float* beta  = (const float*)d_in[4];
    const float* w2    = (const float*)d_in[5];
    const float* b2    = (const float*)d_in[6];
    float* y = (float*)d_out;

    prep_kernel<<<POOLBLKS + WTBLKS, 416>>>(x, w1, w2, b2);
    conv1_kernel<<<dim3(NSL, NB), 224>>>();
    conv2_kernel<<<dim3(4, 2, NB), 224>>>(gamma, beta);
    dw_kernel<<<NB * NC, 224>>>(x, wdyn, y);
}

// round 13
// speedup vs baseline: 1.0187x; 1.0187x over previous
#include <cuda_runtime.h>
#include <math.h>

#define NB 32
#define NC 256
#define NH 56
#define NW 56
#define NP 49
#define CMID 64
#define NSL 8            // conv1 split-K slices (32 channels each)

// ---------------- scratch ----------------
__device__ float g_pooled[NB * NC * NP];
__device__ float g_w1t[2304 * CMID];            // [k=c*9+t][oc]
__device__ float g_w2d[576 * NC];               // [k=c*9+t][oc] (diff oc - (oc+256))
__device__ float g_b2d[NC];
__device__ float g_c1part[NB * CMID * NP * NSL];
__device__ float g_l2part[NB * NC * NP * 2];    // conv2-diff partials (2 ic-slices)

#define W1N (CMID * 2304)
#define W2DN (NC * 576)
#define WTN (W1N + W2DN + NC)
#define POOLBLKS (NB * NC)
#define WTBLKS ((WTN + 415) / 416)

// ---------------- kernel 0: pool (56x56 -> 7x7)  ||  weight prep ----------------
__global__ void prep_kernel(const float* __restrict__ x, const float* __restrict__ w1,
                            const float* __restrict__ w2, const float* __restrict__ b2) {
    const int tid = threadIdx.x;
    if (blockIdx.x < POOLBLKS) {
        __shared__ float srow[392];
        const int bc = blockIdx.x;
        if (tid < 392) {
            const int r = tid / 7, s = tid % 7;
            const float4* p = reinterpret_cast<const float4*>(
                x + (size_t)bc * (NH * NW) + r * NW + s * 8);
            float4 v0 = p[0], v1 = p[1];
            srow[tid] = (v0.x + v0.y + v0.z + v0.w) + (v1.x + v1.y + v1.z + v1.w);
        }
        __syncthreads();
        if (tid < NP) {
            const int wi = tid / 7, wj = tid % 7;
            float s = 0.f;
#pragma unroll
            for (int k = 0; k < 8; k++) s += srow[(wi * 8 + k) * 7 + wj];
            g_pooled[bc * NP + tid] = s * (1.0f / 64.0f);
        }
    } else {
        const int i = (blockIdx.x - POOLBLKS) * 416 + tid;
        if (i < W1N) {
            int oc = i / 2304, k = i % 2304;
            g_w1t[k * CMID + oc] = w1[i];
        } else if (i < W1N + W2DN) {
            int j = i - W1N;
            int oc = j / 576, k = j % 576;
            g_w2d[k * NC + oc] = w2[oc * 576 + k] - w2[(oc + 256) * 576 + k];
        } else if (i < WTN) {
            int oc = i - W1N - W2DN;
            g_b2d[oc] = b2[oc] - b2[oc + 256];
        }
    }
}

// ---------------- kernel 1: conv1 3x3 (256->64), split-K=8 ----------------
__global__ void __launch_bounds__(224, 2) conv1_kernel() {
    __shared__ float s_act[8 * 108];
    __shared__ float s_w[4608];
    const int sl = blockIdx.x, b = blockIdx.y;
    const int tid = threadIdx.x;
    const int r = tid >> 5, lane = tid & 31;

    float acc0[7], acc1[7];
#pragma unroll
    for (int i = 0; i < 7; i++) { acc0[i] = 0.f; acc1[i] = 0.f; }

    for (int chunk = 0; chunk < 4; chunk++) {
        __syncthreads();
        const int c0 = sl * 32 + chunk * 8;
        for (int idx = tid; idx < 8 * 81; idx += 224) {
            const int c = idx / 81, pp = idx % 81;
            const int pr = pp / 9, pc = pp % 9;
            float v = 0.f;
            if (pr >= 1 && pr <= 7 && pc >= 1 && pc <= 7)
                v = g_pooled[(b * NC + c0 + c) * NP + (pr - 1) * 7 + (pc - 1)];
            s_act[c * 108 + pr * 12 + pc] = v;
        }
        {
            const float4* src = reinterpret_cast<const float4*>(g_w1t + c0 * 9 * CMID);
            float4* dst = reinterpret_cast<float4*>(s_w);
            for (int idx = tid; idx < 1152; idx += 224) dst[idx] = src[idx];
        }
        __syncthreads();

#pragma unroll
        for (int cl = 0; cl < 8; cl++) {
            float aa[3][9];
#pragma unroll
            for (int ti = 0; ti < 3; ti++) {
                const float* rp = s_act + cl * 108 + (r + ti) * 12;
                float4 v0 = *reinterpret_cast<const float4*>(rp);
                float4 v1 = *reinterpret_cast<const float4*>(rp + 4);
                aa[ti][0] = v0.x; aa[ti][1] = v0.y; aa[ti][2] = v0.z; aa[ti][3] = v0.w;
                aa[ti][4] = v1.x; aa[ti][5] = v1.y; aa[ti][6] = v1.z; aa[ti][7] = v1.w;
                aa[ti][8] = rp[8];
            }
#pragma unroll
            for (int ti = 0; ti < 3; ti++) {
#pragma unroll
                for (int tj = 0; tj < 3; tj++) {
                    const float2 w = *reinterpret_cast<const float2*>(
                        s_w + (cl * 9 + ti * 3 + tj) * 64 + lane * 2);
#pragma unroll
                    for (int pj = 0; pj < 7; pj++) {
                        acc0[pj] = fmaf(aa[ti][pj + tj], w.x, acc0[pj]);
                        acc1[pj] = fmaf(aa[ti][pj + tj], w.y, acc1[pj]);
                    }
                }
            }
        }
    }
#pragma unroll
    for (int pj = 0; pj < 7; pj++) {
        const int p = r * 7 + pj;
        g_c1part[((size_t)(b * CMID + lane * 2) * NP + p) * NSL + sl] = acc0[pj];
        g_c1part[((size_t)(b * CMID + lane * 2 + 1) * NP + p) * NSL + sl] = acc1[pj];
    }
}

// ---------------- kernel 2: conv2-diff 3x3 (64->256), fused reduce+BN+GELU ----------------
__global__ void __launch_bounds__(224, 2) conv2_kernel(const float* __restrict__ gamma,
                                                       const float* __restrict__ beta) {
    __shared__ float s_act[8 * 108];
    __shared__ float s_w[4608];
    const int ot = blockIdx.x, ks = blockIdx.y, b = blockIdx.z;
    const int tid = threadIdx.x;
    const int r = tid >> 5, lane = tid & 31;

    float acc0[7], acc1[7];
#pragma unroll
    for (int i = 0; i < 7; i++) { acc0[i] = 0.f; acc1[i] = 0.f; }

    for (int chunk = 0; chunk < 4; chunk++) {
        __syncthreads();
        const int ic0 = ks * 32 + chunk * 8;
        for (int idx = tid; idx < 8 * 81; idx += 224) {
            const int c = idx / 81, pp = idx % 81;
            const int pr = pp / 9, pc = pp % 9;
            float v = 0.f;
            if (pr >= 1 && pr <= 7 && pc >= 1 && pc <= 7) {
                const int mid = ic0 + c;
                const float4* p8 = reinterpret_cast<const float4*>(
                    g_c1part + ((size_t)(b * CMID + mid) * NP + (pr - 1) * 7 + (pc - 1)) * NSL);
                float4 u = p8[0], w4 = p8[1];
                float s = ((u.x + u.y) + (u.z + u.w)) + ((w4.x + w4.y) + (w4.z + w4.w));
                float h = s * (gamma[mid] * rsqrtf(1.0f + 1e-5f)) + beta[mid];
                v = 0.5f * h * (1.0f + erff(h * 0.70710678118654752f));
            }
            s_act[c * 108 + pr * 12 + pc] = v;
        }
        for (int idx = tid; idx < 1152; idx += 224) {
            const int kk = idx >> 4, c4 = idx & 15;
            reinterpret_cast<float4*>(s_w)[idx] = *reinterpret_cast<const float4*>(
                g_w2d + (ic0 * 9 + kk) * NC + ot * 64 + c4 * 4);
        }
        __syncthreads();

#pragma unroll
        for (int cl = 0; cl < 8; cl++) {
            float aa[3][9];
#pragma unroll
            for (int ti = 0; ti < 3; ti++) {
                const float* rp = s_act + cl * 108 + (r + ti) * 12;
                float4 v0 = *reinterpret_cast<const float4*>(rp);
                float4 v1 = *reinterpret_cast<const float4*>(rp + 4);
                aa[ti][0] = v0.x; aa[ti][1] = v0.y; aa[ti][2] = v0.z; aa[ti][3] = v0.w;
                aa[ti][4] = v1.x; aa[ti][5] = v1.y; aa[ti][6] = v1.z; aa[ti][7] = v1.w;
                aa[ti][8] = rp[8];
            }
#pragma unroll
            for (int ti = 0; ti < 3; ti++) {
#pragma unroll
                for (int tj = 0; tj < 3; tj++) {
                    const float2 w = *reinterpret_cast<const float2*>(
                        s_w + (cl * 9 + ti * 3 + tj) * 64 + lane * 2);
#pragma unroll
                    for (int pj = 0; pj < 7; pj++) {
                        acc0[pj] = fmaf(aa[ti][pj + tj], w.x, acc0[pj]);
                        acc1[pj] = fmaf(aa[ti][pj + tj], w.y, acc1[pj]);
                    }
                }
            }
        }
    }

    const int oc0 = ot * 64 + lane * 2;
#pragma unroll
    for (int pj = 0; pj < 7; pj++) {
        const int p = r * 7 + pj;
        g_l2part[((size_t)(b * NC + oc0) * NP + p) * 2 + ks] = acc0[pj];
        g_l2part[((size_t)(b * NC + oc0 + 1) * NP + p) * 2 + ks] = acc1[pj];
    }
}

// ---------------- kernel 3: dw 7x7 depthwise, R10 streaming + div-free fill ----------------
// block 224 = 4 row-groups x 56 cols; thread = 14 rows x 1 col.
// Hot loop identical to the proven R10 winner (32 regs, 8 blocks/SM, 92% occ).
// Fill prologue uses incremental rr/cc/ga (1 div at entry) and linear smem index.
__global__ void __launch_bounds__(224, 8) dw_kernel(const float* __restrict__ x,
                                                    const float* __restrict__ wdyn,
                                                    float* __restrict__ y) {
    __shared__ float xs[62 * 62];
    __shared__ float ws[49];
    const int bc = blockIdx.x;
    const int tid = threadIdx.x;

    const float* xp = x + (size_t)bc * (NH * NW);
    {
        int rr = tid / 62;
        int cc = tid - rr * 62;
        int ga = rr * 56 + cc - 171;          // (rr-3)*56 + (cc-3)
#pragma unroll
        for (int it = 0; it < 18; it++) {
            const int idx = it * 224 + tid;
            if (idx < 62 * 62) {
                float v = 0.f;
                if ((unsigned)(rr - 3) < 56u && (unsigned)(cc - 3) < 56u) v = xp[ga];
                xs[idx] = v;
            }
            rr += 3; cc += 38; ga += 206;
            if (cc >= 62) { cc -= 62; rr += 1; ga -= 6; }
        }
    }
    if (tid < 49) {
        const int c = bc & (NC - 1);
        const float2 lp = *reinterpret_cast<const float2*>(g_l2part + ((size_t)bc * NP + tid) * 2);
        const float ld = lp.x + lp.y + g_b2d[c];
        const float s = 1.0f / (1.0f + expf(-ld));
        const float w0 = wdyn[c * NP + tid];
        const float w1 = wdyn[NC * NP + c * NP + tid];
        ws[tid] = s * w0 + (1.0f - s) * w1;
    }
    __syncthreads();

    const int cg = tid / 56;       // 0..3 -> rows cg*14 .. cg*14+13
    const int col = tid % 56;

    float acc[14];
#pragma unroll
    for (int k = 0; k < 14; k++) acc[k] = 0.f;

#pragma unroll
    for (int dj = 0; dj < 7; dj++) {
        float ww[7];
#pragma unroll
        for (int di = 0; di < 7; di++) ww[di] = ws[di * 7 + dj];
        const float* bp = xs + (cg * 14) * 62 + col + dj;
#pragma unroll
        for (int m = 0; m < 20; m++) {
            const float v = bp[m * 62];
#pragma unroll
            for (int di = 0; di < 7; di++) {
                const int k = m - di;
                if (k >= 0 && k < 14)
                    acc[k] = fmaf(v, ww[di], acc[k]);
            }
        }
    }
    float* yp = y + (size_t)bc * (NH * NW);
#pragma unroll
    for (int k = 0; k < 14; k++)
        yp[(cg * 14 + k) * 56 + col] = acc[k];
}

// ---------------- launch ----------------
extern "C" void kernel_launch(void* const* d_in, const int* in_sizes, int n_in,
                              void* d_out, int out_size) {
    const float* x     = (const float*)d_in[0];
    const float* wdyn  = (const float*)d_in[1];
    const float* w1    = (const float*)d_in[2];
    const float* gamma = (const float*)d_in[3];
    const float* beta  = (const float*)d_in[4];
    const float* w2    = (const float*)d_in[5];
    const float* b2    = (const float*)d_in[6];
    float* y = (float*)d_out;

    prep_kernel<<<POOLBLKS + WTBLKS, 416>>>(x, w1, w2, b2);
    conv1_kernel<<<dim3(NSL, NB), 224>>>();
    conv2_kernel<<<dim3(4, 2, NB), 224>>>(gamma, beta);
    dw_kernel<<<NB * NC, 224>>>(x, wdyn, y);
}

// round 14
// speedup vs baseline: 1.0379x; 1.0189x over previous
#include <cuda_runtime.h>
#include <math.h>

#define NB 32
#define NC 256
#define NH 56
#define NW 56
#define NP 49
#define CMID 64
#define NSL 8            // conv1 split-K slices (32 channels each)

// ---------------- scratch ----------------
__device__ float g_pooled[NB * NC * NP];
__device__ float g_w1t[2304 * CMID];            // [k=c*9+t][oc]
__device__ float g_w2d[576 * NC];               // [k=c*9+t][oc] (diff oc - (oc+256))
__device__ float g_b2d[NC];
__device__ float g_c1part[NB * CMID * NP * NSL];
__device__ float g_l2part[NB * NC * NP * 2];    // conv2-diff partials (2 ic-slices)

#define W1N (CMID * 2304)
#define W2DN (NC * 576)
#define WTN (W1N + W2DN + NC)
#define POOLBLKS (NB * NC)
#define WTBLKS ((WTN + 415) / 416)

// ---------------- kernel 0: pool (56x56 -> 7x7)  ||  weight prep ----------------
__global__ void prep_kernel(const float* __restrict__ x, const float* __restrict__ w1,
                            const float* __restrict__ w2, const float* __restrict__ b2) {
    const int tid = threadIdx.x;
    if (blockIdx.x < POOLBLKS) {
        __shared__ float srow[392];
        const int bc = blockIdx.x;
        if (tid < 392) {
            const int r = tid / 7, s = tid % 7;
            const float4* p = reinterpret_cast<const float4*>(
                x + (size_t)bc * (NH * NW) + r * NW + s * 8);
            float4 v0 = p[0], v1 = p[1];
            srow[tid] = (v0.x + v0.y + v0.z + v0.w) + (v1.x + v1.y + v1.z + v1.w);
        }
        __syncthreads();
        if (tid < NP) {
            const int wi = tid / 7, wj = tid % 7;
            float s = 0.f;
#pragma unroll
            for (int k = 0; k < 8; k++) s += srow[(wi * 8 + k) * 7 + wj];
            g_pooled[bc * NP + tid] = s * (1.0f / 64.0f);
        }
    } else {
        const int i = (blockIdx.x - POOLBLKS) * 416 + tid;
        if (i < W1N) {
            int oc = i / 2304, k = i % 2304;
            g_w1t[k * CMID + oc] = w1[i];
        } else if (i < W1N + W2DN) {
            int j = i - W1N;
            int oc = j / 576, k = j % 576;
            g_w2d[k * NC + oc] = w2[oc * 576 + k] - w2[(oc + 256) * 576 + k];
        } else if (i < WTN) {
            int oc = i - W1N - W2DN;
            g_b2d[oc] = b2[oc] - b2[oc + 256];
        }
    }
}

// ---------------- kernel 1: conv1 3x3 (256->64), split-K=8 ----------------
__global__ void __launch_bounds__(224, 2) conv1_kernel() {
    __shared__ float s_act[8 * 108];
    __shared__ float s_w[4608];
    const int sl = blockIdx.x, b = blockIdx.y;
    const int tid = threadIdx.x;
    const int r = tid >> 5, lane = tid & 31;

    float acc0[7], acc1[7];
#pragma unroll
    for (int i = 0; i < 7; i++) { acc0[i] = 0.f; acc1[i] = 0.f; }

    for (int chunk = 0; chunk < 4; chunk++) {
        __syncthreads();
        const int c0 = sl * 32 + chunk * 8;
        for (int idx = tid; idx < 8 * 81; idx += 224) {
            const int c = idx / 81, pp = idx % 81;
            const int pr = pp / 9, pc = pp % 9;
            float v = 0.f;
            if (pr >= 1 && pr <= 7 && pc >= 1 && pc <= 7)
                v = g_pooled[(b * NC + c0 + c) * NP + (pr - 1) * 7 + (pc - 1)];
            s_act[c * 108 + pr * 12 + pc] = v;
        }
        {
            const float4* src = reinterpret_cast<const float4*>(g_w1t + c0 * 9 * CMID);
            float4* dst = reinterpret_cast<float4*>(s_w);
            for (int idx = tid; idx < 1152; idx += 224) dst[idx] = src[idx];
        }
        __syncthreads();

#pragma unroll
        for (int cl = 0; cl < 8; cl++) {
            float aa[3][9];
#pragma unroll
            for (int ti = 0; ti < 3; ti++) {
                const float* rp = s_act + cl * 108 + (r + ti) * 12;
                float4 v0 = *reinterpret_cast<const float4*>(rp);
                float4 v1 = *reinterpret_cast<const float4*>(rp + 4);
                aa[ti][0] = v0.x; aa[ti][1] = v0.y; aa[ti][2] = v0.z; aa[ti][3] = v0.w;
                aa[ti][4] = v1.x; aa[ti][5] = v1.y; aa[ti][6] = v1.z; aa[ti][7] = v1.w;
                aa[ti][8] = rp[8];
            }
#pragma unroll
            for (int ti = 0; ti < 3; ti++) {
#pragma unroll
                for (int tj = 0; tj < 3; tj++) {
                    const float2 w = *reinterpret_cast<const float2*>(
                        s_w + (cl * 9 + ti * 3 + tj) * 64 + lane * 2);
#pragma unroll
                    for (int pj = 0; pj < 7; pj++) {
                        acc0[pj] = fmaf(aa[ti][pj + tj], w.x, acc0[pj]);
                        acc1[pj] = fmaf(aa[ti][pj + tj], w.y, acc1[pj]);
                    }
                }
            }
        }
    }
#pragma unroll
    for (int pj = 0; pj < 7; pj++) {
        const int p = r * 7 + pj;
        g_c1part[((size_t)(b * CMID + lane * 2) * NP + p) * NSL + sl] = acc0[pj];
        g_c1part[((size_t)(b * CMID + lane * 2 + 1) * NP + p) * NSL + sl] = acc1[pj];
    }
}

// ---------------- kernel 2: conv2-diff 3x3 (64->256), fused reduce+BN+GELU ----------------
__global__ void __launch_bounds__(224, 2) conv2_kernel(const float* __restrict__ gamma,
                                                       const float* __restrict__ beta) {
    __shared__ float s_act[8 * 108];
    __shared__ float s_w[4608];
    const int ot = blockIdx.x, ks = blockIdx.y, b = blockIdx.z;
    const int tid = threadIdx.x;
    const int r = tid >> 5, lane = tid & 31;

    float acc0[7], acc1[7];
#pragma unroll
    for (int i = 0; i < 7; i++) { acc0[i] = 0.f; acc1[i] = 0.f; }

    for (int chunk = 0; chunk < 4; chunk++) {
        __syncthreads();
        const int ic0 = ks * 32 + chunk * 8;
        for (int idx = tid; idx < 8 * 81; idx += 224) {
            const int c = idx / 81, pp = idx % 81;
            const int pr = pp / 9, pc = pp % 9;
            float v = 0.f;
            if (pr >= 1 && pr <= 7 && pc >= 1 && pc <= 7) {
                const int mid = ic0 + c;
                const float4* p8 = reinterpret_cast<const float4*>(
                    g_c1part + ((size_t)(b * CMID + mid) * NP + (pr - 1) * 7 + (pc - 1)) * NSL);
                float4 u = p8[0], w4 = p8[1];
                float s = ((u.x + u.y) + (u.z + u.w)) + ((w4.x + w4.y) + (w4.z + w4.w));
                float h = s * (gamma[mid] * rsqrtf(1.0f + 1e-5f)) + beta[mid];
                v = 0.5f * h * (1.0f + erff(h * 0.70710678118654752f));
            }
            s_act[c * 108 + pr * 12 + pc] = v;
        }
        for (int idx = tid; idx < 1152; idx += 224) {
            const int kk = idx >> 4, c4 = idx & 15;
            reinterpret_cast<float4*>(s_w)[idx] = *reinterpret_cast<const float4*>(
                g_w2d + (ic0 * 9 + kk) * NC + ot * 64 + c4 * 4);
        }
        __syncthreads();

#pragma unroll
        for (int cl = 0; cl < 8; cl++) {
            float aa[3][9];
#pragma unroll
            for (int ti = 0; ti < 3; ti++) {
                const float* rp = s_act + cl * 108 + (r + ti) * 12;
                float4 v0 = *reinterpret_cast<const float4*>(rp);
                float4 v1 = *reinterpret_cast<const float4*>(rp + 4);
                aa[ti][0] = v0.x; aa[ti][1] = v0.y; aa[ti][2] = v0.z; aa[ti][3] = v0.w;
                aa[ti][4] = v1.x; aa[ti][5] = v1.y; aa[ti][6] = v1.z; aa[ti][7] = v1.w;
                aa[ti][8] = rp[8];
            }
#pragma unroll
            for (int ti = 0; ti < 3; ti++) {
#pragma unroll
                for (int tj = 0; tj < 3; tj++) {
                    const float2 w = *reinterpret_cast<const float2*>(
                        s_w + (cl * 9 + ti * 3 + tj) * 64 + lane * 2);
#pragma unroll
                    for (int pj = 0; pj < 7; pj++) {
                        acc0[pj] = fmaf(aa[ti][pj + tj], w.x, acc0[pj]);
                        acc1[pj] = fmaf(aa[ti][pj + tj], w.y, acc1[pj]);
                    }
                }
            }
        }
    }

    const int oc0 = ot * 64 + lane * 2;
#pragma unroll
    for (int pj = 0; pj < 7; pj++) {
        const int p = r * 7 + pj;
        g_l2part[((size_t)(b * NC + oc0) * NP + p) * 2 + ks] = acc0[pj];
        g_l2part[((size_t)(b * NC + oc0 + 1) * NP + p) * 2 + ks] = acc1[pj];
    }
}

// ---------------- kernel 3: dw 7x7 depthwise, split-rows streaming ----------------
// 2 blocks per channel (28 rows each). block 224 = 4 row-groups x 56 cols;
// thread = 7 rows x 1 col. Live set ~22 regs at the 8-block/32-reg point ->
// 10 regs of scheduling headroom for cv prefetch batching. Tile 34x62 (8.4KB).
__global__ void __launch_bounds__(224, 8) dw_kernel(const float* __restrict__ x,
                                                    const float* __restrict__ wdyn,
                                                    float* __restrict__ y) {
    __shared__ float xs[34 * 62];
    __shared__ float ws[49];
    const int bc = blockIdx.x >> 1;
    const int row0 = (blockIdx.x & 1) * 28;     // output rows row0..row0+27
    const int tid = threadIdx.x;

    const float* xp = x + (size_t)bc * (NH * NW);
    for (int idx = tid; idx < 34 * 62; idx += 224) {
        const int rr = idx / 62, cc = idx % 62;
        const int gr = row0 + rr - 3, gc = cc - 3;
        float v = 0.f;
        if ((unsigned)gr < 56u && (unsigned)gc < 56u) v = xp[gr * 56 + gc];
        xs[idx] = v;
    }
    if (tid < 49) {
        const int c = bc & (NC - 1);
        const float2 lp = *reinterpret_cast<const float2*>(g_l2part + ((size_t)bc * NP + tid) * 2);
        const float ld = lp.x + lp.y + g_b2d[c];
        const float s = 1.0f / (1.0f + expf(-ld));
        const float w0 = wdyn[c * NP + tid];
        const float w1 = wdyn[NC * NP + c * NP + tid];
        ws[tid] = s * w0 + (1.0f - s) * w1;
    }
    __syncthreads();

    const int cg = tid / 56;       // 0..3 -> tile rows cg*7 .. cg*7+6 (+13 window)
    const int col = tid % 56;
    const int rbase = cg * 7;

    float acc[7];
#pragma unroll
    for (int k = 0; k < 7; k++) acc[k] = 0.f;

#pragma unroll
    for (int dj = 0; dj < 7; dj++) {
        float ww[7];
#pragma unroll
        for (int di = 0; di < 7; di++) ww[di] = ws[di * 7 + dj];
        const float* bp = xs + rbase * 62 + col + dj;
#pragma unroll
        for (int m = 0; m < 13; m++) {
            const float v = bp[m * 62];
#pragma unroll
            for (int di = 0; di < 7; di++) {
                const int k = m - di;
                if (k >= 0 && k < 7)
                    acc[k] = fmaf(v, ww[di], acc[k]);
            }
        }
    }
    float* yp = y + (size_t)bc * (NH * NW);
#pragma unroll
    for (int k = 0; k < 7; k++)
        yp[(row0 + rbase + k) * 56 + col] = acc[k];
}

// ---------------- launch ----------------
extern "C" void kernel_launch(void* const* d_in, const int* in_sizes, int n_in,
                              void* d_out, int out_size) {
    const float* x     = (const float*)d_in[0];
    const float* wdyn  = (const float*)d_in[1];
    const float* w1    = (const float*)d_in[2];
    const float* gamma = (const float*)d_in[3];
    const float* beta  = (const float*)d_in[4];
    const float* w2    = (const float*)d_in[5];
    const float* b2    = (const float*)d_in[6];
    float* y = (float*)d_out;

    prep_kernel<<<POOLBLKS + WTBLKS, 416>>>(x, w1, w2, b2);
    conv1_kernel<<<dim3(NSL, NB), 224>>>();
    conv2_kernel<<<dim3(4, 2, NB), 224>>>(gamma, beta);
    dw_kernel<<<NB * NC * 2, 224>>>(x, wdyn, y);
}

// round 15
// speedup vs baseline: 1.1210x; 1.0800x over previous
#include <cuda_runtime.h>
#include <math.h>

#define NB 32
#define NC 256
#define NH 56
#define NW 56
#define NP 49
#define CMID 64
#define NSL 8            // conv1 split-K slices (32 channels each)

// ---------------- scratch ----------------
__device__ float g_pooled[NB * NC * NP];
__device__ float g_w1t[2304 * CMID];            // [k=c*9+t][oc]
__device__ float g_w2d[576 * NC];               // [k=c*9+t][oc] (diff oc - (oc+256))
__device__ float g_b2d[NC];
__device__ float g_c1part[NB * CMID * NP * NSL];
__device__ float g_l2part[NB * NC * NP * 2];    // conv2-diff partials (2 ic-slices)

#define W1N (CMID * 2304)
#define W2DN (NC * 576)
#define WTN (W1N + W2DN + NC)
#define POOLBLKS (NB * NC)
#define WTBLKS ((WTN + 415) / 416)

// ---------------- kernel 0: pool (56x56 -> 7x7)  ||  weight prep ----------------
__global__ void prep_kernel(const float* __restrict__ x, const float* __restrict__ w1,
                            const float* __restrict__ w2, const float* __restrict__ b2) {
    const int tid = threadIdx.x;
    if (blockIdx.x < POOLBLKS) {
        __shared__ float srow[392];
        const int bc = blockIdx.x;
        if (tid < 392) {
            const int r = tid / 7, s = tid % 7;
            const float4* p = reinterpret_cast<const float4*>(
                x + (size_t)bc * (NH * NW) + r * NW + s * 8);
            float4 v0 = p[0], v1 = p[1];
            srow[tid] = (v0.x + v0.y + v0.z + v0.w) + (v1.x + v1.y + v1.z + v1.w);
        }
        __syncthreads();
        if (tid < NP) {
            const int wi = tid / 7, wj = tid % 7;
            float s = 0.f;
#pragma unroll
            for (int k = 0; k < 8; k++) s += srow[(wi * 8 + k) * 7 + wj];
            g_pooled[bc * NP + tid] = s * (1.0f / 64.0f);
        }
    } else {
        const int i = (blockIdx.x - POOLBLKS) * 416 + tid;
        if (i < W1N) {
            int oc = i / 2304, k = i % 2304;
            g_w1t[k * CMID + oc] = w1[i];
        } else if (i < W1N + W2DN) {
            int j = i - W1N;
            int oc = j / 576, k = j % 576;
            g_w2d[k * NC + oc] = w2[oc * 576 + k] - w2[(oc + 256) * 576 + k];
        } else if (i < WTN) {
            int oc = i - W1N - W2DN;
            g_b2d[oc] = b2[oc] - b2[oc + 256];
        }
    }
}

// ---------------- kernel 1: conv1 3x3 (256->64), split-K=8 ----------------
__global__ void __launch_bounds__(224, 2) conv1_kernel() {
#if __CUDA_ARCH__ >= 900
    cudaGridDependencySynchronize();   // wait for prep (g_pooled, g_w1t)
#endif
    __shared__ float s_act[8 * 108];
    __shared__ float s_w[4608];
    const int sl = blockIdx.x, b = blockIdx.y;
    const int tid = threadIdx.x;
    const int r = tid >> 5, lane = tid & 31;

    float acc0[7], acc1[7];
#pragma unroll
    for (int i = 0; i < 7; i++) { acc0[i] = 0.f; acc1[i] = 0.f; }

    for (int chunk = 0; chunk < 4; chunk++) {
        __syncthreads();
        const int c0 = sl * 32 + chunk * 8;
        for (int idx = tid; idx < 8 * 81; idx += 224) {
            const int c = idx / 81, pp = idx % 81;
            const int pr = pp / 9, pc = pp % 9;
            float v = 0.f;
            if (pr >= 1 && pr <= 7 && pc >= 1 && pc <= 7)
                v = g_pooled[(b * NC + c0 + c) * NP + (pr - 1) * 7 + (pc - 1)];
            s_act[c * 108 + pr * 12 + pc] = v;
        }
        {
            const float4* src = reinterpret_cast<const float4*>(g_w1t + c0 * 9 * CMID);
            float4* dst = reinterpret_cast<float4*>(s_w);
            for (int idx = tid; idx < 1152; idx += 224) dst[idx] = src[idx];
        }
        __syncthreads();

#pragma unroll
        for (int cl = 0; cl < 8; cl++) {
            float aa[3][9];
#pragma unroll
            for (int ti = 0; ti < 3; ti++) {
                const float* rp = s_act + cl * 108 + (r + ti) * 12;
                float4 v0 = *reinterpret_cast<const float4*>(rp);
                float4 v1 = *reinterpret_cast<const float4*>(rp + 4);
                aa[ti][0] = v0.x; aa[ti][1] = v0.y; aa[ti][2] = v0.z; aa[ti][3] = v0.w;
                aa[ti][4] = v1.x; aa[ti][5] = v1.y; aa[ti][6] = v1.z; aa[ti][7] = v1.w;
                aa[ti][8] = rp[8];
            }
#pragma unroll
            for (int ti = 0; ti < 3; ti++) {
#pragma unroll
                for (int tj = 0; tj < 3; tj++) {
                    const float2 w = *reinterpret_cast<const float2*>(
                        s_w + (cl * 9 + ti * 3 + tj) * 64 + lane * 2);
#pragma unroll
                    for (int pj = 0; pj < 7; pj++) {
                        acc0[pj] = fmaf(aa[ti][pj + tj], w.x, acc0[pj]);
                        acc1[pj] = fmaf(aa[ti][pj + tj], w.y, acc1[pj]);
                    }
                }
            }
        }
    }
#pragma unroll
    for (int pj = 0; pj < 7; pj++) {
        const int p = r * 7 + pj;
        g_c1part[((size_t)(b * CMID + lane * 2) * NP + p) * NSL + sl] = acc0[pj];
        g_c1part[((size_t)(b * CMID + lane * 2 + 1) * NP + p) * NSL + sl] = acc1[pj];
    }
}

// ---------------- kernel 2: conv2-diff 3x3 (64->256), fused reduce+BN+GELU ----------------
__global__ void __launch_bounds__(224, 2) conv2_kernel(const float* __restrict__ gamma,
                                                       const float* __restrict__ beta) {
#if __CUDA_ARCH__ >= 900
    cudaGridDependencySynchronize();   // wait for conv1 (g_c1part)
#endif
    __shared__ float s_act[8 * 108];
    __shared__ float s_w[4608];
    const int ot = blockIdx.x, ks = blockIdx.y, b = blockIdx.z;
    const int tid = threadIdx.x;
    const int r = tid >> 5, lane = tid & 31;

    float acc0[7], acc1[7];
#pragma unroll
    for (int i = 0; i < 7; i++) { acc0[i] = 0.f; acc1[i] = 0.f; }

    for (int chunk = 0; chunk < 4; chunk++) {
        __syncthreads();
        const int ic0 = ks * 32 + chunk * 8;
        for (int idx = tid; idx < 8 * 81; idx += 224) {
            const int c = idx / 81, pp = idx % 81;
            const int pr = pp / 9, pc = pp % 9;
            float v = 0.f;
            if (pr >= 1 && pr <= 7 && pc >= 1 && pc <= 7) {
                const int mid = ic0 + c;
                const float4* p8 = reinterpret_cast<const float4*>(
                    g_c1part + ((size_t)(b * CMID + mid) * NP + (pr - 1) * 7 + (pc - 1)) * NSL);
                float4 u = p8[0], w4 = p8[1];
                float s = ((u.x + u.y) + (u.z + u.w)) + ((w4.x + w4.y) + (w4.z + w4.w));
                float h = s * (gamma[mid] * rsqrtf(1.0f + 1e-5f)) + beta[mid];
                v = 0.5f * h * (1.0f + erff(h * 0.70710678118654752f));
            }
            s_act[c * 108 + pr * 12 + pc] = v;
        }
        for (int idx = tid; idx < 1152; idx += 224) {
            const int kk = idx >> 4, c4 = idx & 15;
            reinterpret_cast<float4*>(s_w)[idx] = *reinterpret_cast<const float4*>(
                g_w2d + (ic0 * 9 + kk) * NC + ot * 64 + c4 * 4);
        }
        __syncthreads();

#pragma unroll
        for (int cl = 0; cl < 8; cl++) {
            float aa[3][9];
#pragma unroll
            for (int ti = 0; ti < 3; ti++) {
                const float* rp = s_act + cl * 108 + (r + ti) * 12;
                float4 v0 = *reinterpret_cast<const float4*>(rp);
                float4 v1 = *reinterpret_cast<const float4*>(rp + 4);
                aa[ti][0] = v0.x; aa[ti][1] = v0.y; aa[ti][2] = v0.z; aa[ti][3] = v0.w;
                aa[ti][4] = v1.x; aa[ti][5] = v1.y; aa[ti][6] = v1.z; aa[ti][7] = v1.w;
                aa[ti][8] = rp[8];
            }
#pragma unroll
            for (int ti = 0; ti < 3; ti++) {
#pragma unroll
                for (int tj = 0; tj < 3; tj++) {
                    const float2 w = *reinterpret_cast<const float2*>(
                        s_w + (cl * 9 + ti * 3 + tj) * 64 + lane * 2);
#pragma unroll
                    for (int pj = 0; pj < 7; pj++) {
                        acc0[pj] = fmaf(aa[ti][pj + tj], w.x, acc0[pj]);
                        acc1[pj] = fmaf(aa[ti][pj + tj], w.y, acc1[pj]);
                    }
                }
            }
        }
    }

    const int oc0 = ot * 64 + lane * 2;
#pragma unroll
    for (int pj = 0; pj < 7; pj++) {
        const int p = r * 7 + pj;
        g_l2part[((size_t)(b * NC + oc0) * NP + p) * 2 + ks] = acc0[pj];
        g_l2part[((size_t)(b * NC + oc0 + 1) * NP + p) * 2 + ks] = acc1[pj];
    }
}

// ---------------- kernel 3: dw 7x7 depthwise, R10 streaming + PDL overlap ----------------
// Fill the x tile (independent of prefix) BEFORE cudaGridDependencySynchronize,
// overlapping conv2's execution; then read the gate logits. Hot loop = R10 verbatim.
__global__ void __launch_bounds__(224, 8) dw_kernel(const float* __restrict__ x,
                                                    const float* __restrict__ wdyn,
                                                    float* __restrict__ y) {
    __shared__ float xs[62 * 62];
    __shared__ float ws[49];
    const int bc = blockIdx.x;
    const int tid = threadIdx.x;

    const float* xp = x + (size_t)bc * (NH * NW);
    for (int idx = tid; idx < 62 * 62; idx += 224) {
        const int rr = idx / 62, cc = idx % 62;
        const int gr = rr - 3, gc = cc - 3;
        float v = 0.f;
        if ((unsigned)gr < 56u && (unsigned)gc < 56u) v = xp[gr * 56 + gc];
        xs[idx] = v;
    }
#if __CUDA_ARCH__ >= 900
    cudaGridDependencySynchronize();   // wait for conv2 (g_l2part) AFTER tile fill
#endif
    if (tid < 49) {
        const int c = bc & (NC - 1);
        const float2 lp = *reinterpret_cast<const float2*>(g_l2part + ((size_t)bc * NP + tid) * 2);
        const float ld = lp.x + lp.y + g_b2d[c];
        const float s = 1.0f / (1.0f + expf(-ld));
        const float w0 = wdyn[c * NP + tid];
        const float w1 = wdyn[NC * NP + c * NP + tid];
        ws[tid] = s * w0 + (1.0f - s) * w1;
    }
    __syncthreads();

    const int cg = tid / 56;       // 0..3 -> rows cg*14 .. cg*14+13
    const int col = tid % 56;

    float acc[14];
#pragma unroll
    for (int k = 0; k < 14; k++) acc[k] = 0.f;

#pragma unroll
    for (int dj = 0; dj < 7; dj++) {
        float ww[7];
#pragma unroll
        for (int di = 0; di < 7; di++) ww[di] = ws[di * 7 + dj];
        const float* bp = xs + (cg * 14) * 62 + col + dj;
#pragma unroll
        for (int m = 0; m < 20; m++) {
            const float v = bp[m * 62];
#pragma unroll
            for (int di = 0; di < 7; di++) {
                const int k = m - di;
                if (k >= 0 && k < 14)
                    acc[k] = fmaf(v, ww[di], acc[k]);
            }
        }
    }
    float* yp = y + (size_t)bc * (NH * NW);
#pragma unroll
    for (int k = 0; k < 14; k++)
        yp[(cg * 14 + k) * 56 + col] = acc[k];
}

// ---------------- launch (PDL on consumers) ----------------
static void launch_pdl(dim3 grid, dim3 block, void (*k0)()) {
    cudaLaunchConfig_t cfg = {};
    cfg.gridDim = grid; cfg.blockDim = block; cfg.dynamicSmemBytes = 0; cfg.stream = 0;
    cudaLaunchAttribute attr[1];
    attr[0].id = cudaLaunchAttributeProgrammaticStreamSerialization;
    attr[0].val.programmaticStreamSerializationAllowed = 1;
    cfg.attrs = attr; cfg.numAttrs = 1;
    cudaLaunchKernelEx(&cfg, k0);
}

extern "C" void kernel_launch(void* const* d_in, const int* in_sizes, int n_in,
                              void* d_out, int out_size) {
    const float* x     = (const float*)d_in[0];
    const float* wdyn  = (const float*)d_in[1];
    const float* w1    = (const float*)d_in[2];
    const float* gamma = (const float*)d_in[3];
    const float* beta  = (const float*)d_in[4];
    const float* w2    = (const float*)d_in[5];
    const float* b2    = (const float*)d_in[6];
    float* y = (float*)d_out;

    prep_kernel<<<POOLBLKS + WTBLKS, 416>>>(x, w1, w2, b2);

    launch_pdl(dim3(NSL, NB), dim3(224), conv1_kernel);

    {
        cudaLaunchConfig_t cfg = {};
        cfg.gridDim = dim3(4, 2, NB); cfg.blockDim = dim3(224); cfg.stream = 0;
        cudaLaunchAttribute attr[1];
        attr[0].id = cudaLaunchAttributeProgrammaticStreamSerialization;
        attr[0].val.programmaticStreamSerializationAllowed = 1;
        cfg.attrs = attr; cfg.numAttrs = 1;
        cudaLaunchKernelEx(&cfg, conv2_kernel, gamma, beta);
    }
    {
        cudaLaunchConfig_t cfg = {};
        cfg.gridDim = dim3(NB * NC); cfg.blockDim = dim3(224); cfg.stream = 0;
        cudaLaunchAttribute attr[1];
        attr[0].id = cudaLaunchAttributeProgrammaticStreamSerialization;
        attr[0].val.programmaticStreamSerializationAllowed = 1;
        cfg.attrs = attr; cfg.numAttrs = 1;
        cudaLaunchKernelEx(&cfg, dw_kernel, x, wdyn, y);
    }
}

// round 16
// speedup vs baseline: 1.1924x; 1.0638x over previous
#include <cuda_runtime.h>
#include <math.h>

#define NB 32
#define NC 256
#define NH 56
#define NW 56
#define NP 49
#define CMID 64
#define NSL 8            // conv1 split-K slices (32 channels each)

// ---------------- scratch ----------------
__device__ float g_pooled[NB * NC * NP];
__device__ float g_w1t[2304 * CMID];            // [k=c*9+t][oc]
__device__ float g_w2d[576 * NC];               // [k=c*9+t][oc] (diff oc - (oc+256))
__device__ float g_b2d[NC];
__device__ float g_c1part[NB * CMID * NP * NSL];
__device__ float g_l2part[NB * NC * NP * 2];    // conv2-diff partials (2 ic-slices)

#define W1N (CMID * 2304)
#define W2DN (NC * 576)
#define WTN (W1N + W2DN + NC)
#define POOLBLKS (NB * NC)
#define WTBLKS ((WTN + 415) / 416)

// ---------------- kernel 0: pool (56x56 -> 7x7)  ||  weight prep ----------------
__global__ void prep_kernel(const float* __restrict__ x, const float* __restrict__ w1,
                            const float* __restrict__ w2, const float* __restrict__ b2) {
    const int tid = threadIdx.x;
    if (blockIdx.x < POOLBLKS) {
        __shared__ float srow[392];
        const int bc = blockIdx.x;
        if (tid < 392) {
            const int r = tid / 7, s = tid % 7;
            const float4* p = reinterpret_cast<const float4*>(
                x + (size_t)bc * (NH * NW) + r * NW + s * 8);
            float4 v0 = p[0], v1 = p[1];
            srow[tid] = (v0.x + v0.y + v0.z + v0.w) + (v1.x + v1.y + v1.z + v1.w);
        }
        __syncthreads();
        if (tid < NP) {
            const int wi = tid / 7, wj = tid % 7;
            float s = 0.f;
#pragma unroll
            for (int k = 0; k < 8; k++) s += srow[(wi * 8 + k) * 7 + wj];
            g_pooled[bc * NP + tid] = s * (1.0f / 64.0f);
        }
    } else {
        const int i = (blockIdx.x - POOLBLKS) * 416 + tid;
        if (i < W1N) {
            int oc = i / 2304, k = i % 2304;
            g_w1t[k * CMID + oc] = w1[i];
        } else if (i < W1N + W2DN) {
            int j = i - W1N;
            int oc = j / 576, k = j % 576;
            g_w2d[k * NC + oc] = w2[oc * 576 + k] - w2[(oc + 256) * 576 + k];
        } else if (i < WTN) {
            int oc = i - W1N - W2DN;
            g_b2d[oc] = b2[oc] - b2[oc + 256];
        }
    }
}

// ---------------- kernel 1: conv1 3x3 (256->64), split-K=8 ----------------
__global__ void __launch_bounds__(224, 2) conv1_kernel() {
#if __CUDA_ARCH__ >= 900
    cudaGridDependencySynchronize();   // wait for prep (g_pooled, g_w1t)
#endif
    __shared__ float s_act[8 * 108];
    __shared__ float s_w[4608];
    const int sl = blockIdx.x, b = blockIdx.y;
    const int tid = threadIdx.x;
    const int r = tid >> 5, lane = tid & 31;

    float acc0[7], acc1[7];
#pragma unroll
    for (int i = 0; i < 7; i++) { acc0[i] = 0.f; acc1[i] = 0.f; }

    for (int chunk = 0; chunk < 4; chunk++) {
        __syncthreads();
        const int c0 = sl * 32 + chunk * 8;
        for (int idx = tid; idx < 8 * 81; idx += 224) {
            const int c = idx / 81, pp = idx % 81;
            const int pr = pp / 9, pc = pp % 9;
            float v = 0.f;
            if (pr >= 1 && pr <= 7 && pc >= 1 && pc <= 7)
                v = g_pooled[(b * NC + c0 + c) * NP + (pr - 1) * 7 + (pc - 1)];
            s_act[c * 108 + pr * 12 + pc] = v;
        }
        {
            const float4* src = reinterpret_cast<const float4*>(g_w1t + c0 * 9 * CMID);
            float4* dst = reinterpret_cast<float4*>(s_w);
            for (int idx = tid; idx < 1152; idx += 224) dst[idx] = src[idx];
        }
        __syncthreads();

#pragma unroll
        for (int cl = 0; cl < 8; cl++) {
            float aa[3][9];
#pragma unroll
            for (int ti = 0; ti < 3; ti++) {
                const float* rp = s_act + cl * 108 + (r + ti) * 12;
                float4 v0 = *reinterpret_cast<const float4*>(rp);
                float4 v1 = *reinterpret_cast<const float4*>(rp + 4);
                aa[ti][0] = v0.x; aa[ti][1] = v0.y; aa[ti][2] = v0.z; aa[ti][3] = v0.w;
                aa[ti][4] = v1.x; aa[ti][5] = v1.y; aa[ti][6] = v1.z; aa[ti][7] = v1.w;
                aa[ti][8] = rp[8];
            }
#pragma unroll
            for (int ti = 0; ti < 3; ti++) {
#pragma unroll
                for (int tj = 0; tj < 3; tj++) {
                    const float2 w = *reinterpret_cast<const float2*>(
                        s_w + (cl * 9 + ti * 3 + tj) * 64 + lane * 2);
#pragma unroll
                    for (int pj = 0; pj < 7; pj++) {
                        acc0[pj] = fmaf(aa[ti][pj + tj], w.x, acc0[pj]);
                        acc1[pj] = fmaf(aa[ti][pj + tj], w.y, acc1[pj]);
                    }
                }
            }
        }
    }
#pragma unroll
    for (int pj = 0; pj < 7; pj++) {
        const int p = r * 7 + pj;
        g_c1part[((size_t)(b * CMID + lane * 2) * NP + p) * NSL + sl] = acc0[pj];
        g_c1part[((size_t)(b * CMID + lane * 2 + 1) * NP + p) * NSL + sl] = acc1[pj];
    }
}

// ---------------- kernel 2: conv2-diff 3x3 (64->256), fused reduce+BN+GELU ----------------
__global__ void __launch_bounds__(224, 2) conv2_kernel(const float* __restrict__ gamma,
                                                       const float* __restrict__ beta) {
#if __CUDA_ARCH__ >= 900
    cudaGridDependencySynchronize();   // wait for conv1 (g_c1part)
#endif
    __shared__ float s_act[8 * 108];
    __shared__ float s_w[4608];
    const int ot = blockIdx.x, ks = blockIdx.y, b = blockIdx.z;
    const int tid = threadIdx.x;
    const int r = tid >> 5, lane = tid & 31;

    float acc0[7], acc1[7];
#pragma unroll
    for (int i = 0; i < 7; i++) { acc0[i] = 0.f; acc1[i] = 0.f; }

    for (int chunk = 0; chunk < 4; chunk++) {
        __syncthreads();
        const int ic0 = ks * 32 + chunk * 8;
        for (int idx = tid; idx < 8 * 81; idx += 224) {
            const int c = idx / 81, pp = idx % 81;
            const int pr = pp / 9, pc = pp % 9;
            float v = 0.f;
            if (pr >= 1 && pr <= 7 && pc >= 1 && pc <= 7) {
                const int mid = ic0 + c;
                const float4* p8 = reinterpret_cast<const float4*>(
                    g_c1part + ((size_t)(b * CMID + mid) * NP + (pr - 1) * 7 + (pc - 1)) * NSL);
                float4 u = p8[0], w4 = p8[1];
                float s = ((u.x + u.y) + (u.z + u.w)) + ((w4.x + w4.y) + (w4.z + w4.w));
                float h = s * (gamma[mid] * rsqrtf(1.0f + 1e-5f)) + beta[mid];
                v = 0.5f * h * (1.0f + erff(h * 0.70710678118654752f));
            }
            s_act[c * 108 + pr * 12 + pc] = v;
        }
        for (int idx = tid; idx < 1152; idx += 224) {
            const int kk = idx >> 4, c4 = idx & 15;
            reinterpret_cast<float4*>(s_w)[idx] = *reinterpret_cast<const float4*>(
                g_w2d + (ic0 * 9 + kk) * NC + ot * 64 + c4 * 4);
        }
        __syncthreads();

#pragma unroll
        for (int cl = 0; cl < 8; cl++) {
            float aa[3][9];
#pragma unroll
            for (int ti = 0; ti < 3; ti++) {
                const float* rp = s_act + cl * 108 + (r + ti) * 12;
                float4 v0 = *reinterpret_cast<const float4*>(rp);
                float4 v1 = *reinterpret_cast<const float4*>(rp + 4);
                aa[ti][0] = v0.x; aa[ti][1] = v0.y; aa[ti][2] = v0.z; aa[ti][3] = v0.w;
                aa[ti][4] = v1.x; aa[ti][5] = v1.y; aa[ti][6] = v1.z; aa[ti][7] = v1.w;
                aa[ti][8] = rp[8];
            }
#pragma unroll
            for (int ti = 0; ti < 3; ti++) {
#pragma unroll
                for (int tj = 0; tj < 3; tj++) {
                    const float2 w = *reinterpret_cast<const float2*>(
                        s_w + (cl * 9 + ti * 3 + tj) * 64 + lane * 2);
#pragma unroll
                    for (int pj = 0; pj < 7; pj++) {
                        acc0[pj] = fmaf(aa[ti][pj + tj], w.x, acc0[pj]);
                        acc1[pj] = fmaf(aa[ti][pj + tj], w.y, acc1[pj]);
                    }
                }
            }
        }
    }

    const int oc0 = ot * 64 + lane * 2;
#pragma unroll
    for (int pj = 0; pj < 7; pj++) {
        const int p = r * 7 + pj;
        g_l2part[((size_t)(b * NC + oc0) * NP + p) * 2 + ks] = acc0[pj];
        g_l2part[((size_t)(b * NC + oc0 + 1) * NP + p) * 2 + ks] = acc1[pj];
    }
}

// ---------------- kernel 3: dw 7x7 depthwise, 28-rows/thread streaming + PDL ----------------
// block 112 = 2 row-groups x 56 cols; thread = 28 rows x 1 col.
// Per dj: ww[7] + stream 34 values, each feeding up to 7 of acc[28].
// ~65 instr/output (vs 82 in the 14-row version). Live ~43 regs; cap 48 via
// __launch_bounds__(112, 12) -> no spills, 65.6% occ (issue ceiling is ~65% anyway).
__global__ void __launch_bounds__(112, 12) dw_kernel(const float* __restrict__ x,
                                                     const float* __restrict__ wdyn,
                                                     float* __restrict__ y) {
    __shared__ float xs[62 * 62];
    __shared__ float ws[49];
    const int bc = blockIdx.x;
    const int tid = threadIdx.x;

    const float* xp = x + (size_t)bc * (NH * NW);
    for (int idx = tid; idx < 62 * 62; idx += 112) {
        const int rr = idx / 62, cc = idx % 62;
        const int gr = rr - 3, gc = cc - 3;
        float v = 0.f;
        if ((unsigned)gr < 56u && (unsigned)gc < 56u) v = xp[gr * 56 + gc];
        xs[idx] = v;
    }
#if __CUDA_ARCH__ >= 900
    cudaGridDependencySynchronize();   // wait for conv2 (g_l2part) AFTER tile fill
#endif
    if (tid < 49) {
        const int c = bc & (NC - 1);
        const float2 lp = *reinterpret_cast<const float2*>(g_l2part + ((size_t)bc * NP + tid) * 2);
        const float ld = lp.x + lp.y + g_b2d[c];
        const float s = 1.0f / (1.0f + expf(-ld));
        const float w0 = wdyn[c * NP + tid];
        const float w1 = wdyn[NC * NP + c * NP + tid];
        ws[tid] = s * w0 + (1.0f - s) * w1;
    }
    __syncthreads();

    const int cg = tid / 56;       // 0..1 -> rows cg*28 .. cg*28+27
    const int col = tid % 56;

    float acc[28];
#pragma unroll
    for (int k = 0; k < 28; k++) acc[k] = 0.f;

#pragma unroll
    for (int dj = 0; dj < 7; dj++) {
        float ww[7];
#pragma unroll
        for (int di = 0; di < 7; di++) ww[di] = ws[di * 7 + dj];
        const float* bp = xs + (cg * 28) * 62 + col + dj;
#pragma unroll
        for (int m = 0; m < 34; m++) {
            const float v = bp[m * 62];
#pragma unroll
            for (int di = 0; di < 7; di++) {
                const int k = m - di;
                if (k >= 0 && k < 28)
                    acc[k] = fmaf(v, ww[di], acc[k]);
            }
        }
    }
    float* yp = y + (size_t)bc * (NH * NW);
#pragma unroll
    for (int k = 0; k < 28; k++)
        yp[(cg * 28 + k) * 56 + col] = acc[k];
}

// ---------------- launch (PDL on consumers) ----------------
static void launch_pdl(dim3 grid, dim3 block, void (*k0)()) {
    cudaLaunchConfig_t cfg = {};
    cfg.gridDim = grid; cfg.blockDim = block; cfg.dynamicSmemBytes = 0; cfg.stream = 0;
    cudaLaunchAttribute attr[1];
    attr[0].id = cudaLaunchAttributeProgrammaticStreamSerialization;
    attr[0].val.programmaticStreamSerializationAllowed = 1;
    cfg.attrs = attr; cfg.numAttrs = 1;
    cudaLaunchKernelEx(&cfg, k0);
}

extern "C" void kernel_launch(void* const* d_in, const int* in_sizes, int n_in,
                              void* d_out, int out_size) {
    const float* x     = (const float*)d_in[0];
    const float* wdyn  = (const float*)d_in[1];
    const float* w1    = (const float*)d_in[2];
    const float* gamma = (const float*)d_in[3];
    const float* beta  = (const float*)d_in[4];
    const float* w2    = (const float*)d_in[5];
    const float* b2    = (const float*)d_in[6];
    float* y = (float*)d_out;

    prep_kernel<<<POOLBLKS + WTBLKS, 416>>>(x, w1, w2, b2);

    launch_pdl(dim3(NSL, NB), dim3(224), conv1_kernel);

    {
        cudaLaunchConfig_t cfg = {};
        cfg.gridDim = dim3(4, 2, NB); cfg.blockDim = dim3(224); cfg.stream = 0;
        cudaLaunchAttribute attr[1];
        attr[0].id = cudaLaunchAttributeProgrammaticStreamSerialization;
        attr[0].val.programmaticStreamSerializationAllowed = 1;
        cfg.attrs = attr; cfg.numAttrs = 1;
        cudaLaunchKernelEx(&cfg, conv2_kernel, gamma, beta);
    }
    {
        cudaLaunchConfig_t cfg = {};
        cfg.gridDim = dim3(NB * NC); cfg.blockDim = dim3(112); cfg.stream = 0;
        cudaLaunchAttribute attr[1];
        attr[0].id = cudaLaunchAttributeProgrammaticStreamSerialization;
        attr[0].val.programmaticStreamSerializationAllowed = 1;
        cfg.attrs = attr; cfg.numAttrs = 1;
        cudaLaunchKernelEx(&cfg, dw_kernel, x, wdyn, y);
    }
}